// round 9
// baseline (speedup 1.0000x reference)
#include <cuda_runtime.h>

#define HW_    262144          // 512*512 floats per channel
#define C_     9
#define N_     16
#define NCH_   144             // N_*C_
#define NSPL_  8               // stream splits per channel
#define ST_    256             // stream kernel threads
#define RT_    512             // refine kernel threads
#define SLOT_  128             // stream per-thread candidate slots (exact worst case)

// Scratch (device globals — no allocation allowed)
__device__ unsigned long long g_cand[(size_t)NCH_ * HW_];
// Bitmap (per channel, 8192 words): word = s*1024 + q*256 + t, bit = ob2*16 + j*4 + e
//   <-> element f4 = s*8192 + (q*2+ob2)*1024 + j*256 + t   (s:0..7 q:0..3 ob2:0..1 j:0..3)
__device__ unsigned g_bitmap[NCH_ * 8192];
__device__ unsigned g_cnthi[NCH_ * NSPL_];   // per-split above-hi counts
__device__ unsigned g_capcnt[NCH_ * 2048];   // per-list (s*256+t) capture counts

// Order-preserving float->uint key (ascending key == ascending float)
static __device__ __forceinline__ unsigned f2key(float f) {
    unsigned u = __float_as_uint(f);
    return (u & 0x80000000u) ? ~u : (u | 0x80000000u);
}

// ---------------- stream kernel: 1152 CTAs x 256 threads ----------------
__global__ void __launch_bounds__(ST_, 6) k_stream(const float* __restrict__ inp,
                                                   const float* __restrict__ ratio)
{
    __shared__ unsigned swr[8];
    int bx = blockIdx.x;               // ch*8 + s
    int ch = bx >> 3, s = bx & 7, n = ch / C_;
    int tid = threadIdx.x, w = tid >> 5, lane = tid & 31;

    // k: replicate reference f32 arithmetic exactly
    float f_p = floorf(ratio[n] * 262144.0f);
    int k = (int)floorf(f_p * 0.15f);
    bool k0 = (k <= 0);

    // Analytic bracket (N(0,1) quantile). Correctness guaranteed by the
    // count-check + full-rescan fallback in k_refine, not by normality.
    float lo_f, hi_f;
    if (k0) {
        lo_f = hi_f = 1.0f;            // reference: thr = 1.0 when k == 0 (strict >, exact)
    } else {
        float q = (float)k * (1.0f / 262144.0f);
        float t = sqrtf(-2.0f * logf(q));               // A&S 26.2.23
        float z = t - (2.515517f + 0.802853f * t + 0.010328f * t * t)
                    / (1.0f + 1.432788f * t + 0.189269f * t * t + 0.001308f * t * t * t);
        float phi = 0.3989423f * expf(-0.5f * z * z);
        float delta = 0.008f + 10.0f * sqrtf((float)k) / (262144.0f * phi);
        lo_f = z - delta; hi_f = z + delta;
    }

    const float4* p = (const float4*)(inp + (size_t)ch * HW_) + s * 8192;
    unsigned* gbw = g_bitmap + ch * 8192 + s * 1024;
    unsigned long long* myc = g_cand + (size_t)ch * HW_
                            + (size_t)s * 32768 + (size_t)tid * SLOT_;
    unsigned mycnt = 0;
    int mycap = 0;

    #pragma unroll 1
    for (int q = 0; q < 4; q++) {
        unsigned word = 0;
        #pragma unroll
        for (int ob2 = 0; ob2 < 2; ob2++) {
            int base = (q * 2 + ob2) * 1024;
            float4 v0 = p[base + tid];
            float4 v1 = p[base + 256 + tid];
            float4 v2 = p[base + 512 + tid];
            float4 v3 = p[base + 768 + tid];
            #pragma unroll
            for (int j = 0; j < 4; j++) {
                float4 v = (j == 0) ? v0 : (j == 1) ? v1 : (j == 2) ? v2 : v3;
                unsigned hi4 = (unsigned)(v.x > hi_f) | ((unsigned)(v.y > hi_f) << 1)
                             | ((unsigned)(v.z > hi_f) << 2) | ((unsigned)(v.w > hi_f) << 3);
                unsigned lo4 = (unsigned)(v.x > lo_f) | ((unsigned)(v.y > lo_f) << 1)
                             | ((unsigned)(v.z > lo_f) << 2) | ((unsigned)(v.w > lo_f) << 3);
                word |= hi4 << (ob2 * 16 + j * 4);
                unsigned cn = lo4 & ~hi4;
                if (cn) {                               // rare (~0.2-2%)
                    unsigned f4 = (unsigned)(s * 8192 + base + j * 256 + tid);
                    if (cn & 1u) myc[mycap++] = ((unsigned long long)f2key(v.x) << 32) | (f4 * 4 + 0);
                    if (cn & 2u) myc[mycap++] = ((unsigned long long)f2key(v.y) << 32) | (f4 * 4 + 1);
                    if (cn & 4u) myc[mycap++] = ((unsigned long long)f2key(v.z) << 32) | (f4 * 4 + 2);
                    if (cn & 8u) myc[mycap++] = ((unsigned long long)f2key(v.w) << 32) | (f4 * 4 + 3);
                }
            }
        }
        mycnt += __popc(word);
        gbw[q * 256 + tid] = word;                      // coalesced, no cross-lane ops
    }
    g_capcnt[ch * 2048 + s * 256 + tid] = (unsigned)mycap;
    #pragma unroll
    for (int off = 16; off; off >>= 1) mycnt += __shfl_down_sync(0xffffffffu, mycnt, off);
    if (lane == 0) swr[w] = mycnt;
    __syncthreads();
    if (w == 0) {
        unsigned c = (lane < 8) ? swr[lane] : 0u;
        #pragma unroll
        for (int off = 4; off; off >>= 1) c += __shfl_down_sync(0xffffffffu, c, off);
        if (lane == 0) g_cnthi[ch * 8 + s] = c;
    }
}

// Block-wide "find bin containing rank-from-top", RT_=512 threads, nb in {2048,1024}.
static __device__ __forceinline__ void bfind(
    unsigned* hist, int nb, unsigned rank,
    unsigned* sgrp, unsigned* aux, int tid, int lane, int w)
{
    int B = nb >> 9;                        // 4 or 2 bins per thread
    unsigned s = 0;
    #pragma unroll
    for (int j = 0; j < 4; j++) if (j < B) s += hist[tid * B + j];
    sgrp[tid] = s;
    __syncthreads();
    if (w == 0) {
        unsigned sup = 0;
        #pragma unroll
        for (int j = 0; j < 16; j++) sup += sgrp[lane * 16 + j];
        unsigned v = sup;                   // inclusive suffix scan (lane31 = top bins)
        #pragma unroll
        for (int off = 1; off < 32; off <<= 1) {
            unsigned t = __shfl_down_sync(0xffffffffu, v, off);
            if (lane + off < 32) v += t;
        }
        unsigned cumAbove = v - sup;
        bool hit = (cumAbove < rank) && (cumAbove + sup >= rank);
        unsigned bal = __ballot_sync(0xffffffffu, hit);
        int Ls = __ffs(bal) - 1;
        if (lane == Ls) {
            unsigned cum = cumAbove;
            for (int g = Ls * 16 + 15; ; g--) {
                unsigned sg = sgrp[g];
                if (cum + sg >= rank) {
                    for (int b = g * B + B - 1; ; b--) {
                        unsigned h = hist[b];
                        if (cum + h >= rank) { aux[0] = (unsigned)b; aux[1] = rank - cum; break; }
                        cum += h;
                    }
                    break;
                }
                cum += sg;
            }
        }
    }
    __syncthreads();
}

// ---------------- refine kernel: 144 CTAs x 512 threads ----------------
__global__ void __launch_bounds__(RT_) k_refine(const float* __restrict__ inp,
                                                const float* __restrict__ ratio)
{
    __shared__ unsigned hist[2048];
    __shared__ unsigned sgrp[RT_];
    __shared__ unsigned swr[16];
    __shared__ unsigned aux[4];   // [0]=bin [1]=rank [2]=cnt_hi [3]=m

    int ch = blockIdx.x, n = ch / C_;
    int tid = threadIdx.x, w = tid >> 5, lane = tid & 31;

    float f_p = floorf(ratio[n] * 262144.0f);
    int k = (int)floorf(f_p * 0.15f);
    if (k <= 0) return;                    // bitmap already exact (thr = 1.0)

    // channel totals
    if (tid == 0) {
        unsigned ct = 0;
        #pragma unroll
        for (int s = 0; s < 8; s++) ct += g_cnthi[ch * 8 + s];
        aux[2] = ct;
    }
    const unsigned long long* lst[4];
    unsigned lcnt[4];
    unsigned msum = 0;
    #pragma unroll
    for (int i = 0; i < 4; i++) {          // lists {tid, tid+512, tid+1024, tid+1536}
        int L = i * RT_ + tid;
        int s = L >> 8, t = L & 255;
        lcnt[i] = g_capcnt[ch * 2048 + L];
        lst[i]  = g_cand + (size_t)ch * HW_ + (size_t)s * 32768 + (size_t)t * SLOT_;
        msum += lcnt[i];
    }
    #pragma unroll
    for (int off = 16; off; off >>= 1) msum += __shfl_down_sync(0xffffffffu, msum, off);
    if (lane == 0) swr[w] = msum;
    __syncthreads();
    if (w == 0) {
        unsigned c = (lane < 16) ? swr[lane] : 0u;
        #pragma unroll
        for (int off = 8; off; off >>= 1) c += __shfl_down_sync(0xffffffffu, c, off);
        if (lane == 0) aux[3] = c;
    }
    __syncthreads();
    unsigned cnt_hi = aux[2], m = aux[3];
    unsigned rank;
    bool ok = (cnt_hi < (unsigned)k) && (cnt_hi + m >= (unsigned)k);
    if (ok) {
        rank = (unsigned)k - cnt_hi;
    } else {
        // Deterministic full-rescan fallback (never for N(0,1) data; always correct).
        unsigned* gbch = g_bitmap + ch * 8192;
        for (int i = tid; i < 8192; i += RT_) gbch[i] = 0;
        unsigned long long* mc2 = g_cand + (size_t)ch * HW_ + (size_t)tid * 512;
        const float4* pc = (const float4*)(inp + (size_t)ch * HW_);
        int cap = 0;
        for (int i = 0; i < 128; i++) {
            unsigned f4 = (unsigned)(i * RT_ + tid);
            float4 v = pc[f4];
            mc2[cap++] = ((unsigned long long)f2key(v.x) << 32) | (f4 * 4 + 0);
            mc2[cap++] = ((unsigned long long)f2key(v.y) << 32) | (f4 * 4 + 1);
            mc2[cap++] = ((unsigned long long)f2key(v.z) << 32) | (f4 * 4 + 2);
            mc2[cap++] = ((unsigned long long)f2key(v.w) << 32) | (f4 * 4 + 3);
        }
        lst[0] = mc2; lcnt[0] = 512;
        lcnt[1] = lcnt[2] = lcnt[3] = 0;
        rank = (unsigned)k;
        __syncthreads();
    }

    // pass 1: key bits [31:21]
    for (int i = tid; i < 2048; i += RT_) hist[i] = 0;
    __syncthreads();
    #pragma unroll
    for (int i = 0; i < 4; i++)
        for (unsigned j = 0; j < lcnt[i]; j++)
            atomicAdd(&hist[(unsigned)(lst[i][j] >> 32) >> 21], 1u);
    __syncthreads();
    bfind(hist, 2048, rank, sgrp, aux, tid, lane, w);
    unsigned bA = aux[0], rA = aux[1];
    __syncthreads();

    // pass 2: bits [20:10]
    for (int i = tid; i < 2048; i += RT_) hist[i] = 0;
    __syncthreads();
    #pragma unroll
    for (int i = 0; i < 4; i++)
        for (unsigned j = 0; j < lcnt[i]; j++) {
            unsigned key = (unsigned)(lst[i][j] >> 32);
            if ((key >> 21) == bA) atomicAdd(&hist[(key >> 10) & 0x7FFu], 1u);
        }
    __syncthreads();
    bfind(hist, 2048, rA, sgrp, aux, tid, lane, w);
    unsigned bB = aux[0], rB = aux[1];
    __syncthreads();

    // pass 3: bits [9:0]
    for (int i = tid; i < 1024; i += RT_) hist[i] = 0;
    __syncthreads();
    #pragma unroll
    for (int i = 0; i < 4; i++)
        for (unsigned j = 0; j < lcnt[i]; j++) {
            unsigned key = (unsigned)(lst[i][j] >> 32);
            if ((key >> 21) == bA && ((key >> 10) & 0x7FFu) == bB)
                atomicAdd(&hist[key & 0x3FFu], 1u);
        }
    __syncthreads();
    bfind(hist, 1024, rB, sgrp, aux, tid, lane, w);
    unsigned thrkey = (bA << 21) | (bB << 10) | aux[0];   // exact key of k-th largest
    __syncthreads();

    // fixups: candidates strictly above threshold -> set bitmap bit
    unsigned* gbch = g_bitmap + ch * 8192;
    #pragma unroll
    for (int i = 0; i < 4; i++)
        for (unsigned j = 0; j < lcnt[i]; j++) {
            unsigned long long cc = lst[i][j];
            if ((unsigned)(cc >> 32) > thrkey) {
                unsigned pos = (unsigned)cc;
                unsigned f4 = pos >> 2, e = pos & 3u;
                unsigned s = f4 >> 13, rem = f4 & 8191u;
                unsigned ob = rem >> 10, jj = (rem >> 8) & 3u, t = rem & 255u;
                atomicOr(&gbch[s * 1024 + (ob >> 1) * 256 + t],
                         1u << ((ob & 1u) * 16 + jj * 4 + e));
            }
        }
}

// ---------------- mask kernel: 512 CTAs x 256 threads ----------------
__global__ void __launch_bounds__(256) k_mask(const float* __restrict__ x,
                                              float* __restrict__ out)
{
    int gidx = blockIdx.x * 256 + threadIdx.x;       // 0..131071
    int nn = gidx >> 13;
    int wp = gidx & 8191;
    const unsigned* bm = g_bitmap + (size_t)nn * C_ * 8192 + wp;
    unsigned wrd = 0;
    #pragma unroll
    for (int c = 0; c < C_; c++) wrd |= __ldg(bm + (size_t)c * 8192);
    int s = wp >> 10, q = (wp >> 8) & 3, t = wp & 255;
    const float4* xp = (const float4*)x + ((size_t)nn << 16);
    float4*       op = (float4*)out     + ((size_t)nn << 16);
    #pragma unroll
    for (int ob2 = 0; ob2 < 2; ob2++) {
        #pragma unroll
        for (int j = 0; j < 4; j++) {
            int f4 = s * 8192 + (q * 2 + ob2) * 1024 + j * 256 + t;
            unsigned nib = (wrd >> (ob2 * 16 + j * 4)) & 0xFu;
            float4 xv = xp[f4];
            float4 o;
            o.x = (nib & 1u) ? 0.0f : xv.x;
            o.y = (nib & 2u) ? 0.0f : xv.y;
            o.z = (nib & 4u) ? 0.0f : xv.z;
            o.w = (nib & 8u) ? 0.0f : xv.w;
            op[f4] = o;
        }
    }
}

extern "C" void kernel_launch(void* const* d_in, const int* in_sizes, int n_in,
                              void* d_out, int out_size) {
    const float* inp   = (const float*)d_in[0];   // [16,9,512,512]
    const float* x     = (const float*)d_in[1];   // [16,1,512,512]
    const float* ratio = (const float*)d_in[2];   // [16]
    float* out = (float*)d_out;

    k_stream<<<NCH_ * NSPL_, ST_>>>(inp, ratio);
    k_refine<<<NCH_, RT_>>>(inp, ratio);
    k_mask<<<N_ * 8192 / 256, 256>>>(x, out);
}

// round 10
// speedup vs baseline: 1.2161x; 1.2161x over previous
#include <cuda_runtime.h>

#define HW_    262144          // 512*512 floats per channel
#define C_     9
#define N_     16
#define NCH_   144             // N_*C_
#define NT_    1024            // threads per CTA
#define SLOTS_ 256             // retry-mode per-thread gmem slots (exact: HW_/NT_)
#define WSLOT_ 256             // per-warp smem candidate slots

// Scratch (device globals — no allocation allowed)
__device__ unsigned long long g_cand[(size_t)NCH_ * HW_];  // retry mode only
// Bitmap (per channel, 8192 words): word[ob*1024 + t], bit j*4+e
//   <-> element ((ob*8192 + j*1024 + t)*4 + e),  ob:0..7, j:0..7, t:0..1023
__device__ unsigned g_bitmap[NCH_ * (HW_ / 32)];
__device__ unsigned g_bar_cnt;                             // grid barrier (zero-init)
__device__ unsigned g_bar_flag;

// Order-preserving float->uint key (ascending key == ascending float)
static __device__ __forceinline__ unsigned f2key(float f) {
    unsigned u = __float_as_uint(f);
    return (u & 0x80000000u) ? ~u : (u | 0x80000000u);
}

// Block-wide "find bin containing rank-from-top" over hist[0..nb), nb in {2048,1024}.
// Result: aux[0]=bin, aux[1]=remaining rank (1-indexed in bin). All NT_ threads call.
static __device__ __forceinline__ void block_find_bin(
    unsigned* hist, int nb, unsigned rank,
    unsigned* sgrp, unsigned* aux, int tid, int lane, int w)
{
    unsigned s = (nb == 2048) ? (hist[tid * 2] + hist[tid * 2 + 1]) : hist[tid];
    sgrp[tid] = s;
    __syncthreads();
    if (w == 0) {
        unsigned sup = 0;
        #pragma unroll 4
        for (int j = 0; j < 32; j++) sup += sgrp[lane * 32 + j];
        unsigned v = sup;                    // inclusive suffix scan (lane31 = top bins)
        #pragma unroll
        for (int off = 1; off < 32; off <<= 1) {
            unsigned t = __shfl_down_sync(0xffffffffu, v, off);
            if (lane + off < 32) v += t;
        }
        unsigned cumAbove = v - sup;
        bool hit = (cumAbove < rank) && (cumAbove + sup >= rank);
        unsigned bal = __ballot_sync(0xffffffffu, hit);
        int Ls = __ffs(bal) - 1;
        if (lane == Ls) {
            unsigned cum = cumAbove;
            for (int g = Ls * 32 + 31; ; g--) {
                unsigned sg = sgrp[g];
                if (cum + sg >= rank) {
                    int B = (nb == 2048) ? 2 : 1;
                    for (int b = g * B + B - 1; ; b--) {
                        unsigned h = hist[b];
                        if (cum + h >= rank) { aux[0] = (unsigned)b; aux[1] = rank - cum; break; }
                        cum += h;
                    }
                    break;
                }
                cum += sg;
            }
        }
    }
    __syncthreads();
}

__global__ void __launch_bounds__(NT_) k_fused(const float* __restrict__ inp,
                                               const float* __restrict__ ratio,
                                               const float* __restrict__ x,
                                               float* __restrict__ out)
{
    extern __shared__ unsigned char smem_raw[];
    unsigned long long* scand = (unsigned long long*)smem_raw;        // 32*256*8 = 64KB
    unsigned* hist = (unsigned*)(smem_raw + 32 * WSLOT_ * 8);         // 2048
    unsigned* sgrp = hist + 2048;                                     // 1024
    unsigned* wcnt = sgrp + 1024;                                     // 32
    unsigned* aux  = wcnt + 32;                                       // 4

    int ch = blockIdx.x, n = ch / C_;
    int tid = threadIdx.x, w = tid >> 5, lane = tid & 31;

    // k: replicate reference f32 arithmetic exactly
    float f_p = floorf(ratio[n] * 262144.0f);
    int k = (int)floorf(f_p * 0.15f);
    bool k0 = (k <= 0);

    const float4* p = (const float4*)(inp + (size_t)ch * HW_);

    // Analytic bracket around the k-th largest for N(0,1)-like data. Correctness
    // is guaranteed by the count-check + full-capture retry, not by normality.
    float lo_f, hi_f;
    if (k0) {
        lo_f = hi_f = 1.0f;            // reference: thr = 1.0 when k == 0 (strict >, exact)
    } else {
        float q = (float)k * (1.0f / 262144.0f);
        float t = sqrtf(-2.0f * logf(q));               // A&S 26.2.23
        float z = t - (2.515517f + 0.802853f * t + 0.010328f * t * t)
                    / (1.0f + 1.432788f * t + 0.189269f * t * t + 0.001308f * t * t * t);
        float phi = 0.3989423f * expf(-0.5f * z * z);
        float delta = 0.008f + 10.0f * sqrtf((float)k) / (262144.0f * phi);
        lo_f = z - delta; hi_f = z + delta;
    }

    unsigned* gbch = g_bitmap + (size_t)ch * 8192;
    unsigned long long* myc = g_cand + (size_t)ch * HW_ + (size_t)tid * SLOTS_;
    unsigned long long* wbuf = scand + (size_t)w * WSLOT_;

    if (tid < 32) wcnt[tid] = 0;
    if (tid == 0) aux[0] = 0;
    __syncthreads();

    // ---- attempt 0: stream with smem candidate capture ----
    {
        unsigned mycnt = 0;
        #pragma unroll 1
        for (int ob = 0; ob < 8; ob++) {           // 8 outer blocks of 8*NT_ float4s
            int base = ob * 8 * NT_;
            float4 v0 = __ldcs(&p[base + tid]);
            float4 v1 = __ldcs(&p[base + NT_ + tid]);
            float4 v2 = __ldcs(&p[base + 2 * NT_ + tid]);
            float4 v3 = __ldcs(&p[base + 3 * NT_ + tid]);
            float4 v4 = __ldcs(&p[base + 4 * NT_ + tid]);
            float4 v5 = __ldcs(&p[base + 5 * NT_ + tid]);
            float4 v6 = __ldcs(&p[base + 6 * NT_ + tid]);
            float4 v7 = __ldcs(&p[base + 7 * NT_ + tid]);
            unsigned word = 0;
            #pragma unroll
            for (int j = 0; j < 8; j++) {
                float4 v = (j == 0) ? v0 : (j == 1) ? v1 : (j == 2) ? v2 : (j == 3) ? v3
                         : (j == 4) ? v4 : (j == 5) ? v5 : (j == 6) ? v6 : v7;
                unsigned hi4 = (unsigned)(v.x > hi_f) | ((unsigned)(v.y > hi_f) << 1)
                             | ((unsigned)(v.z > hi_f) << 2) | ((unsigned)(v.w > hi_f) << 3);
                unsigned lo4 = (unsigned)(v.x > lo_f) | ((unsigned)(v.y > lo_f) << 1)
                             | ((unsigned)(v.z > lo_f) << 2) | ((unsigned)(v.w > lo_f) << 3);
                word |= hi4 << (j * 4);
                unsigned cn = lo4 & ~hi4;
                if (cn) {                           // rare (~0.2-2%)
                    unsigned f4 = (unsigned)(base + j * NT_ + tid);
                    if (cn & 1u) { unsigned i2 = atomicAdd(&wcnt[w], 1u);
                        if (i2 < WSLOT_) wbuf[i2] = ((unsigned long long)f2key(v.x) << 32) | (f4 * 4 + 0); }
                    if (cn & 2u) { unsigned i2 = atomicAdd(&wcnt[w], 1u);
                        if (i2 < WSLOT_) wbuf[i2] = ((unsigned long long)f2key(v.y) << 32) | (f4 * 4 + 1); }
                    if (cn & 4u) { unsigned i2 = atomicAdd(&wcnt[w], 1u);
                        if (i2 < WSLOT_) wbuf[i2] = ((unsigned long long)f2key(v.z) << 32) | (f4 * 4 + 2); }
                    if (cn & 8u) { unsigned i2 = atomicAdd(&wcnt[w], 1u);
                        if (i2 < WSLOT_) wbuf[i2] = ((unsigned long long)f2key(v.w) << 32) | (f4 * 4 + 3); }
                }
            }
            mycnt += __popc(word);
            gbch[ob * NT_ + tid] = word;            // coalesced, no cross-lane ops
        }
        #pragma unroll
        for (int off = 16; off; off >>= 1) mycnt += __shfl_down_sync(0xffffffffu, mycnt, off);
        if (lane == 0) atomicAdd(&aux[0], mycnt);
    }
    __syncthreads();
    unsigned cnt_hi = aux[0];
    if (w == 0) {                                   // sum + max of per-warp counts
        unsigned c = wcnt[lane], mx = c, sm2 = c;
        #pragma unroll
        for (int off = 16; off; off >>= 1) {
            sm2 += __shfl_down_sync(0xffffffffu, sm2, off);
            unsigned o = __shfl_down_sync(0xffffffffu, mx, off);
            mx = (o > mx) ? o : mx;
        }
        if (lane == 0) { aux[1] = sm2; aux[2] = mx; }
    }
    __syncthreads();
    unsigned m = aux[1], maxw = aux[2];

    bool smode = true;
    int mycap = 0;
    if (!k0) {
        bool ok = (cnt_hi < (unsigned)k) && (cnt_hi + m >= (unsigned)k) && (maxw <= WSLOT_);
        if (!ok) {
            // ---- deterministic full-capture retry (never for N(0,1); always correct) ----
            smode = false;
            __syncthreads();
            #pragma unroll 1
            for (int ob = 0; ob < 8; ob++) {
                int base = ob * 8 * NT_;
                #pragma unroll
                for (int j = 0; j < 8; j++) {
                    unsigned f4 = (unsigned)(base + j * NT_ + tid);
                    float4 v = __ldcs(&p[f4]);
                    myc[mycap++] = ((unsigned long long)f2key(v.x) << 32) | (f4 * 4 + 0);
                    myc[mycap++] = ((unsigned long long)f2key(v.y) << 32) | (f4 * 4 + 1);
                    myc[mycap++] = ((unsigned long long)f2key(v.z) << 32) | (f4 * 4 + 2);
                    myc[mycap++] = ((unsigned long long)f2key(v.w) << 32) | (f4 * 4 + 3);
                }
                gbch[ob * NT_ + tid] = 0;           // no definite bits; fixups set all
            }
            cnt_hi = 0;
            __syncthreads();
        }
    }

    // ---- exact threshold among candidates (11+11+10-bit radix), then fixups ----
    if (!k0) {
        unsigned r = (unsigned)k - cnt_hi;
        for (int i = tid; i < 2048; i += NT_) hist[i] = 0;
        __syncthreads();
        if (smode) {
            for (int ww = 0; ww < 32; ww++) {
                unsigned c = wcnt[ww];
                for (unsigned i = tid; i < c; i += NT_)
                    atomicAdd(&hist[(unsigned)(scand[ww * WSLOT_ + i] >> 32) >> 21], 1u);
            }
        } else {
            for (int i = 0; i < mycap; i++)
                atomicAdd(&hist[(unsigned)(myc[i] >> 32) >> 21], 1u);
        }
        __syncthreads();
        block_find_bin(hist, 2048, r, sgrp, aux, tid, lane, w);
        unsigned bA = aux[0], rA = aux[1];
        __syncthreads();

        for (int i = tid; i < 2048; i += NT_) hist[i] = 0;
        __syncthreads();
        if (smode) {
            for (int ww = 0; ww < 32; ww++) {
                unsigned c = wcnt[ww];
                for (unsigned i = tid; i < c; i += NT_) {
                    unsigned key = (unsigned)(scand[ww * WSLOT_ + i] >> 32);
                    if ((key >> 21) == bA) atomicAdd(&hist[(key >> 10) & 0x7FFu], 1u);
                }
            }
        } else {
            for (int i = 0; i < mycap; i++) {
                unsigned key = (unsigned)(myc[i] >> 32);
                if ((key >> 21) == bA) atomicAdd(&hist[(key >> 10) & 0x7FFu], 1u);
            }
        }
        __syncthreads();
        block_find_bin(hist, 2048, rA, sgrp, aux, tid, lane, w);
        unsigned bB = aux[0], rB = aux[1];
        __syncthreads();

        for (int i = tid; i < 1024; i += NT_) hist[i] = 0;
        __syncthreads();
        if (smode) {
            for (int ww = 0; ww < 32; ww++) {
                unsigned c = wcnt[ww];
                for (unsigned i = tid; i < c; i += NT_) {
                    unsigned key = (unsigned)(scand[ww * WSLOT_ + i] >> 32);
                    if ((key >> 21) == bA && ((key >> 10) & 0x7FFu) == bB)
                        atomicAdd(&hist[key & 0x3FFu], 1u);
                }
            }
        } else {
            for (int i = 0; i < mycap; i++) {
                unsigned key = (unsigned)(myc[i] >> 32);
                if ((key >> 21) == bA && ((key >> 10) & 0x7FFu) == bB)
                    atomicAdd(&hist[key & 0x3FFu], 1u);
            }
        }
        __syncthreads();
        block_find_bin(hist, 1024, rB, sgrp, aux, tid, lane, w);
        unsigned thrkey = (bA << 21) | (bB << 10) | aux[0];    // exact k-th largest
        __syncthreads();

        // Fixups: candidates strictly above threshold -> set bit in bitmap
        if (smode) {
            for (int ww = 0; ww < 32; ww++) {
                unsigned c = wcnt[ww];
                for (unsigned i = tid; i < c; i += NT_) {
                    unsigned long long cc = scand[ww * WSLOT_ + i];
                    if ((unsigned)(cc >> 32) > thrkey) {
                        unsigned pos = (unsigned)cc & 0x3FFFFu;
                        unsigned f4 = pos >> 2, e = pos & 3u;
                        unsigned t  = f4 & 1023u, j = (f4 >> 10) & 7u, ob = f4 >> 13;
                        atomicOr(&gbch[ob * NT_ + t], 1u << (j * 4 + e));
                    }
                }
            }
        } else {
            for (int i = 0; i < mycap; i++) {
                unsigned long long cc = myc[i];
                if ((unsigned)(cc >> 32) > thrkey) {
                    unsigned pos = (unsigned)cc & 0x3FFFFu;
                    unsigned f4 = pos >> 2, e = pos & 3u;
                    unsigned t  = f4 & 1023u, j = (f4 >> 10) & 7u, ob = f4 >> 13;
                    atomicOr(&gbch[ob * NT_ + t], 1u << (j * 4 + e));
                }
            }
        }
    }

    // ---- software grid barrier (144 resident CTAs; graph-replay safe) ----
    __threadfence();
    __syncthreads();
    if (tid == 0) {
        unsigned gen = *(volatile unsigned*)&g_bar_flag;
        unsigned t = atomicAdd(&g_bar_cnt, 1u);
        if (t == NCH_ - 1) {
            atomicExch(&g_bar_cnt, 0u);          // reset for next graph replay
            __threadfence();
            atomicAdd(&g_bar_flag, 1u);
        } else {
            while (*(volatile unsigned*)&g_bar_flag == gen) __nanosleep(64);
        }
        __threadfence();
    }
    __syncthreads();

    // ---- phase 2: per-thread OR of 9 channel words, apply to 8 float4s of x ----
    int gidx = blockIdx.x * NT_ + tid;               // 147456 threads, 131072 items
    if (gidx < N_ * 8192) {
        int nn = gidx >> 13;
        int wp = gidx & 8191;
        int ob = wp >> 10, t = wp & 1023;
        const unsigned* bm = g_bitmap + (size_t)nn * C_ * 8192 + wp;
        unsigned wrd = 0;
        #pragma unroll
        for (int c = 0; c < C_; c++) wrd |= __ldg(bm + (size_t)c * 8192);
        const float4* xp = (const float4*)x + ((size_t)nn << 16) + ob * 8192 + t;
        float4*       op = (float4*)out     + ((size_t)nn << 16) + ob * 8192 + t;
        #pragma unroll
        for (int j = 0; j < 8; j++) {
            float4 xv = __ldcs(&xp[j * 1024]);
            unsigned nib = (wrd >> (j * 4)) & 0xFu;
            float4 o;
            o.x = (nib & 1u) ? 0.0f : xv.x;
            o.y = (nib & 2u) ? 0.0f : xv.y;
            o.z = (nib & 4u) ? 0.0f : xv.z;
            o.w = (nib & 8u) ? 0.0f : xv.w;
            __stcs(&op[j * 1024], o);
        }
    }
}

extern "C" void kernel_launch(void* const* d_in, const int* in_sizes, int n_in,
                              void* d_out, int out_size) {
    const float* inp   = (const float*)d_in[0];   // [16,9,512,512]
    const float* x     = (const float*)d_in[1];   // [16,1,512,512]
    const float* ratio = (const float*)d_in[2];   // [16]
    float* out = (float*)d_out;

    const int smem_bytes = 32 * WSLOT_ * 8 + (2048 + 1024 + 32 + 4) * 4;   // ~77.9KB
    cudaFuncSetAttribute(k_fused, cudaFuncAttributeMaxDynamicSharedMemorySize, smem_bytes);
    k_fused<<<NCH_, NT_, smem_bytes>>>(inp, ratio, x, out);
}

// round 11
// speedup vs baseline: 1.4889x; 1.2243x over previous
#include <cuda_runtime.h>

#define HW_    262144          // 512*512 floats per channel
#define C_     9
#define N_     16
#define NCH_   144             // N_*C_
#define NT_    1024            // threads per CTA
#define SLOTS_ 256             // per-thread candidate slots (exact: HW_/NT_, retry-safe)
#define HALF_  32768           // float4s per channel half

// Scratch (device globals — no allocation allowed)
__device__ unsigned long long g_cand[(size_t)NCH_ * HW_];  // per-thread regions
// Bitmap (per channel, 8192 words): word[ob*1024 + t], bit half*16 + j*4 + e
//   <-> element f4 = half*32768 + ob*4096 + j*1024 + t   (ob:0..7, j:0..3, half:0..1)
__device__ unsigned g_bitmap[NCH_ * (HW_ / 32)];
__device__ unsigned g_bar_cnt;                             // grid barrier (zero-init)
__device__ unsigned g_bar_flag;

// Order-preserving float->uint key (ascending key == ascending float)
static __device__ __forceinline__ unsigned f2key(float f) {
    unsigned u = __float_as_uint(f);
    return (u & 0x80000000u) ? ~u : (u | 0x80000000u);
}

// Block-wide "find bin containing rank-from-top" over hist[0..nb), nb in {2048,1024}.
// Result: aux[0]=bin, aux[1]=remaining rank (1-indexed in bin). All NT_ threads call.
static __device__ __forceinline__ void block_find_bin(
    unsigned* hist, int nb, unsigned rank,
    unsigned* sgrp, unsigned* aux, int tid, int lane, int w)
{
    unsigned s = (nb == 2048) ? (hist[tid * 2] + hist[tid * 2 + 1]) : hist[tid];
    sgrp[tid] = s;
    __syncthreads();
    if (w == 0) {
        unsigned sup = 0;
        #pragma unroll 4
        for (int j = 0; j < 32; j++) sup += sgrp[lane * 32 + j];
        unsigned v = sup;                    // inclusive suffix scan (lane31 = top bins)
        #pragma unroll
        for (int off = 1; off < 32; off <<= 1) {
            unsigned t = __shfl_down_sync(0xffffffffu, v, off);
            if (lane + off < 32) v += t;
        }
        unsigned cumAbove = v - sup;
        bool hit = (cumAbove < rank) && (cumAbove + sup >= rank);
        unsigned bal = __ballot_sync(0xffffffffu, hit);
        int Ls = __ffs(bal) - 1;
        if (lane == Ls) {
            unsigned cum = cumAbove;
            for (int g = Ls * 32 + 31; ; g--) {
                unsigned sg = sgrp[g];
                if (cum + sg >= rank) {
                    int B = (nb == 2048) ? 2 : 1;
                    for (int b = g * B + B - 1; ; b--) {
                        unsigned h = hist[b];
                        if (cum + h >= rank) { aux[0] = (unsigned)b; aux[1] = rank - cum; break; }
                        cum += h;
                    }
                    break;
                }
                cum += sg;
            }
        }
    }
    __syncthreads();
}

__global__ void __launch_bounds__(NT_) k_fused(const float* __restrict__ inp,
                                               const float* __restrict__ ratio,
                                               const float* __restrict__ x,
                                               float* __restrict__ out)
{
    __shared__ unsigned hist[2048];
    __shared__ unsigned sgrp[NT_];
    __shared__ unsigned aux[4];        // [0]=cnt_hi / bin, [1]=m / rank

    int ch = blockIdx.x, n = ch / C_;
    int tid = threadIdx.x, w = tid >> 5, lane = tid & 31;

    // k: replicate reference f32 arithmetic exactly
    float f_p = floorf(ratio[n] * 262144.0f);
    int k = (int)floorf(f_p * 0.15f);
    bool k0 = (k <= 0);

    const float4* p = (const float4*)(inp + (size_t)ch * HW_);
    const float INF = __int_as_float(0x7F800000);

    // Analytic bracket around the k-th largest for N(0,1)-like data. Correctness
    // is guaranteed by the count-check + full-range retry, not by normality.
    float lo_f, hi_f;
    if (k0) {
        lo_f = hi_f = 1.0f;            // reference: thr = 1.0 when k == 0 (strict >, exact)
    } else {
        float q = (float)k * (1.0f / 262144.0f);
        float t = sqrtf(-2.0f * logf(q));               // A&S 26.2.23
        float z = t - (2.515517f + 0.802853f * t + 0.010328f * t * t)
                    / (1.0f + 1.432788f * t + 0.189269f * t * t + 0.001308f * t * t * t);
        float phi = 0.3989423f * expf(-0.5f * z * z);
        float delta = 0.008f + 10.0f * sqrtf((float)k) / (262144.0f * phi);
        lo_f = z - delta; hi_f = z + delta;
    }

    unsigned long long* myc = g_cand + (size_t)ch * HW_ + (size_t)tid * SLOTS_;
    unsigned* gbch = g_bitmap + (size_t)ch * 8192;
    unsigned cnt_hi, m;
    int mycap;
    for (int attempt = 0; ; attempt++) {
        if (tid == 0) { aux[0] = 0; aux[1] = 0; }
        __syncthreads();
        unsigned mycnt = 0;
        mycap = 0;
        #pragma unroll 1
        for (int ob = 0; ob < 8; ob++) {           // two independent half-streams
            int base = ob * 4 * NT_;               // 0..28672 step 4096
            float4 a0 = p[base + tid];
            float4 a1 = p[base + NT_ + tid];
            float4 a2 = p[base + 2 * NT_ + tid];
            float4 a3 = p[base + 3 * NT_ + tid];
            float4 b0 = p[HALF_ + base + tid];
            float4 b1 = p[HALF_ + base + NT_ + tid];
            float4 b2 = p[HALF_ + base + 2 * NT_ + tid];
            float4 b3 = p[HALF_ + base + 3 * NT_ + tid];
            unsigned word = 0;
            #pragma unroll
            for (int u = 0; u < 8; u++) {
                int half = u >> 2, j = u & 3;
                float4 v = (u == 0) ? a0 : (u == 1) ? a1 : (u == 2) ? a2 : (u == 3) ? a3
                         : (u == 4) ? b0 : (u == 5) ? b1 : (u == 6) ? b2 : b3;
                unsigned hi4 = (unsigned)(v.x > hi_f) | ((unsigned)(v.y > hi_f) << 1)
                             | ((unsigned)(v.z > hi_f) << 2) | ((unsigned)(v.w > hi_f) << 3);
                unsigned lo4 = (unsigned)(v.x > lo_f) | ((unsigned)(v.y > lo_f) << 1)
                             | ((unsigned)(v.z > lo_f) << 2) | ((unsigned)(v.w > lo_f) << 3);
                word |= hi4 << (half * 16 + j * 4);
                unsigned cn = lo4 & ~hi4;
                if (cn) {                           // rare (~0.2-2%)
                    int idx4 = half * HALF_ + base + j * NT_ + tid;
                    if (cn & 1u) myc[mycap++] = ((unsigned long long)f2key(v.x) << 32) | (unsigned)(idx4 * 4 + 0);
                    if (cn & 2u) myc[mycap++] = ((unsigned long long)f2key(v.y) << 32) | (unsigned)(idx4 * 4 + 1);
                    if (cn & 4u) myc[mycap++] = ((unsigned long long)f2key(v.z) << 32) | (unsigned)(idx4 * 4 + 2);
                    if (cn & 8u) myc[mycap++] = ((unsigned long long)f2key(v.w) << 32) | (unsigned)(idx4 * 4 + 3);
                }
            }
            mycnt += __popc(word);
            gbch[ob * NT_ + tid] = word;            // coalesced, no cross-lane ops
        }
        // Block totals
        unsigned mc = (unsigned)mycap;
        #pragma unroll
        for (int off = 16; off; off >>= 1) {
            mycnt += __shfl_down_sync(0xffffffffu, mycnt, off);
            mc    += __shfl_down_sync(0xffffffffu, mc, off);
        }
        if (lane == 0) { atomicAdd(&aux[0], mycnt); atomicAdd(&aux[1], mc); }
        __syncthreads();
        cnt_hi = aux[0]; m = aux[1];
        if (k0) break;
        if ((cnt_hi < (unsigned)k && cnt_hi + m >= (unsigned)k) || attempt >= 1) break;
        lo_f = -INF; hi_f = INF;       // deterministic widen (count-check guarantee)
        __syncthreads();
    }

    // ---- exact threshold among candidates (11+11+10-bit radix), then fixups ----
    if (!k0) {
        unsigned r = (unsigned)k - cnt_hi;
        for (int i = tid; i < 2048; i += NT_) hist[i] = 0;
        __syncthreads();
        for (int i = 0; i < mycap; i++)
            atomicAdd(&hist[(unsigned)(myc[i] >> 32) >> 21], 1u);
        __syncthreads();
        block_find_bin(hist, 2048, r, sgrp, aux, tid, lane, w);
        unsigned bA = aux[0], rA = aux[1];
        __syncthreads();

        for (int i = tid; i < 2048; i += NT_) hist[i] = 0;
        __syncthreads();
        for (int i = 0; i < mycap; i++) {
            unsigned key = (unsigned)(myc[i] >> 32);
            if ((key >> 21) == bA) atomicAdd(&hist[(key >> 10) & 0x7FFu], 1u);
        }
        __syncthreads();
        block_find_bin(hist, 2048, rA, sgrp, aux, tid, lane, w);
        unsigned bB = aux[0], rB = aux[1];
        __syncthreads();

        for (int i = tid; i < 1024; i += NT_) hist[i] = 0;
        __syncthreads();
        for (int i = 0; i < mycap; i++) {
            unsigned key = (unsigned)(myc[i] >> 32);
            if ((key >> 21) == bA && ((key >> 10) & 0x7FFu) == bB)
                atomicAdd(&hist[key & 0x3FFu], 1u);
        }
        __syncthreads();
        block_find_bin(hist, 1024, rB, sgrp, aux, tid, lane, w);
        unsigned thrkey = (bA << 21) | (bB << 10) | aux[0];    // exact k-th largest
        __syncthreads();

        // Fixups: candidates above exact threshold -> set bit in bitmap
        for (int i = 0; i < mycap; i++) {
            unsigned long long cc = myc[i];
            if ((unsigned)(cc >> 32) > thrkey) {
                unsigned pos = (unsigned)cc & 0x3FFFFu;
                unsigned f4 = pos >> 2, e = pos & 3u;
                unsigned half = f4 >> 15, f4h = f4 & 32767u;
                unsigned ob = f4h >> 12, j = (f4h >> 10) & 3u, t = f4h & 1023u;
                atomicOr(&gbch[ob * NT_ + t], 1u << (half * 16 + j * 4 + e));
            }
        }
    }

    // ---- software grid barrier (144 resident CTAs; graph-replay safe) ----
    __threadfence();
    __syncthreads();
    if (tid == 0) {
        unsigned gen = *(volatile unsigned*)&g_bar_flag;
        unsigned t = atomicAdd(&g_bar_cnt, 1u);
        if (t == NCH_ - 1) {
            atomicExch(&g_bar_cnt, 0u);          // reset for next graph replay
            __threadfence();
            atomicAdd(&g_bar_flag, 1u);
        } else {
            while (*(volatile unsigned*)&g_bar_flag == gen) __nanosleep(64);
        }
        __threadfence();
    }
    __syncthreads();

    // ---- phase 2: per-thread OR of 9 channel words, apply to 8 float4s of x ----
    int gidx = blockIdx.x * NT_ + tid;               // 147456 threads, 131072 items
    if (gidx < N_ * 8192) {
        int nn = gidx >> 13;
        int wp = gidx & 8191;
        int ob = wp >> 10, t = wp & 1023;
        const unsigned* bm = g_bitmap + (size_t)nn * C_ * 8192 + wp;
        unsigned wrd = 0;
        #pragma unroll
        for (int c = 0; c < C_; c++) wrd |= __ldg(bm + (size_t)c * 8192);
        const float4* xp = (const float4*)x + ((size_t)nn << 16);
        float4*       op = (float4*)out     + ((size_t)nn << 16);
        #pragma unroll
        for (int half = 0; half < 2; half++) {
            #pragma unroll
            for (int j = 0; j < 4; j++) {
                int f4 = half * HALF_ + ob * 4096 + j * 1024 + t;
                unsigned nib = (wrd >> (half * 16 + j * 4)) & 0xFu;
                float4 xv = xp[f4];
                float4 o;
                o.x = (nib & 1u) ? 0.0f : xv.x;
                o.y = (nib & 2u) ? 0.0f : xv.y;
                o.z = (nib & 4u) ? 0.0f : xv.z;
                o.w = (nib & 8u) ? 0.0f : xv.w;
                op[f4] = o;
            }
        }
    }
}

extern "C" void kernel_launch(void* const* d_in, const int* in_sizes, int n_in,
                              void* d_out, int out_size) {
    const float* inp   = (const float*)d_in[0];   // [16,9,512,512]
    const float* x     = (const float*)d_in[1];   // [16,1,512,512]
    const float* ratio = (const float*)d_in[2];   // [16]
    float* out = (float*)d_out;

    k_fused<<<NCH_, NT_>>>(inp, ratio, x, out);
}

// round 12
// speedup vs baseline: 1.5398x; 1.0342x over previous
#include <cuda_runtime.h>

#define HW_    262144          // 512*512 floats per channel
#define C_     9
#define N_     16
#define NCH_   144             // N_*C_
#define NT_    1024            // threads per CTA
#define SLOTS_ 256             // per-thread candidate slots (exact: HW_/NT_, retry-safe)

// Scratch (device globals — no allocation allowed)
__device__ unsigned long long g_cand[(size_t)NCH_ * HW_];  // per-thread regions
// Bitmap (per channel, 8192 words): word[ob*1024 + t], bit j*4+e
//   <-> element ((ob*8192 + j*1024 + t)*4 + e),  ob:0..7, j:0..7, t:0..1023
__device__ unsigned g_bitmap[NCH_ * (HW_ / 32)];
__device__ unsigned g_bar_cnt;                             // grid barrier (zero-init)
__device__ unsigned g_bar_flag;

// Order-preserving float->uint key (ascending key == ascending float)
static __device__ __forceinline__ unsigned f2key(float f) {
    unsigned u = __float_as_uint(f);
    return (u & 0x80000000u) ? ~u : (u | 0x80000000u);
}

// Packed f32x2 fma: returns fma(a2, b2, c2) per 32-bit lane (one FFMA2)
static __device__ __forceinline__ unsigned long long fma2(
    unsigned long long a, unsigned long long b, unsigned long long c) {
    unsigned long long d;
    asm("fma.rn.f32x2 %0, %1, %2, %3;" : "=l"(d) : "l"(a), "l"(b), "l"(c));
    return d;
}

// Sign-bit movemask of 4 packed f32 (d01 = lanes x,y; d23 = lanes z,w) -> nibble
// bit0=sign(x) bit1=sign(y) bit2=sign(z) bit3=sign(w). Carry-free multiply trick.
static __device__ __forceinline__ unsigned mm4(unsigned long long d01,
                                               unsigned long long d23) {
    unsigned a = __byte_perm((unsigned)d01, (unsigned)(d01 >> 32), 0x0073);
    unsigned b = __byte_perm((unsigned)d23, (unsigned)(d23 >> 32), 0x0073);
    unsigned w = __byte_perm(a, b, 0x5410);   // sign bytes of x,y,z,w
    return ((w & 0x80808080u) * 0x00204081u) >> 28;
}

// Block-wide "find bin containing rank-from-top" over hist[0..nb), nb in {2048,1024}.
// Result: aux[0]=bin, aux[1]=remaining rank (1-indexed in bin). All NT_ threads call.
static __device__ __forceinline__ void block_find_bin(
    unsigned* hist, int nb, unsigned rank,
    unsigned* sgrp, unsigned* aux, int tid, int lane, int w)
{
    unsigned s = (nb == 2048) ? (hist[tid * 2] + hist[tid * 2 + 1]) : hist[tid];
    sgrp[tid] = s;
    __syncthreads();
    if (w == 0) {
        unsigned sup = 0;
        #pragma unroll 4
        for (int j = 0; j < 32; j++) sup += sgrp[lane * 32 + j];
        unsigned v = sup;                    // inclusive suffix scan (lane31 = top bins)
        #pragma unroll
        for (int off = 1; off < 32; off <<= 1) {
            unsigned t = __shfl_down_sync(0xffffffffu, v, off);
            if (lane + off < 32) v += t;
        }
        unsigned cumAbove = v - sup;
        bool hit = (cumAbove < rank) && (cumAbove + sup >= rank);
        unsigned bal = __ballot_sync(0xffffffffu, hit);
        int Ls = __ffs(bal) - 1;
        if (lane == Ls) {
            unsigned cum = cumAbove;
            for (int g = Ls * 32 + 31; ; g--) {
                unsigned sg = sgrp[g];
                if (cum + sg >= rank) {
                    int B = (nb == 2048) ? 2 : 1;
                    for (int b = g * B + B - 1; ; b--) {
                        unsigned h = hist[b];
                        if (cum + h >= rank) { aux[0] = (unsigned)b; aux[1] = rank - cum; break; }
                        cum += h;
                    }
                    break;
                }
                cum += sg;
            }
        }
    }
    __syncthreads();
}

__global__ void __launch_bounds__(NT_) k_fused(const float* __restrict__ inp,
                                               const float* __restrict__ ratio,
                                               const float* __restrict__ x,
                                               float* __restrict__ out)
{
    __shared__ unsigned hist[2048];
    __shared__ unsigned sgrp[NT_];
    __shared__ unsigned aux[4];        // [0]=cnt_hi / bin, [1]=m / rank

    int ch = blockIdx.x, n = ch / C_;
    int tid = threadIdx.x, w = tid >> 5, lane = tid & 31;

    // k: replicate reference f32 arithmetic exactly
    float f_p = floorf(ratio[n] * 262144.0f);
    int k = (int)floorf(f_p * 0.15f);
    bool k0 = (k <= 0);

    const ulonglong2* p = (const ulonglong2*)(inp + (size_t)ch * HW_);
    const float INF = __int_as_float(0x7F800000);

    // Analytic bracket around the k-th largest for N(0,1)-like data. Correctness
    // is guaranteed by the count-check + full-range retry, not by normality.
    float lo_f, hi_f;
    if (k0) {
        lo_f = hi_f = 1.0f;            // reference: thr = 1.0 when k == 0 (strict >, exact)
    } else {
        float q = (float)k * (1.0f / 262144.0f);
        float t = sqrtf(-2.0f * logf(q));               // A&S 26.2.23
        float z = t - (2.515517f + 0.802853f * t + 0.010328f * t * t)
                    / (1.0f + 1.432788f * t + 0.189269f * t * t + 0.001308f * t * t * t);
        float phi = 0.3989423f * expf(-0.5f * z * z);
        float delta = 0.008f + 10.0f * sqrtf((float)k) / (262144.0f * phi);
        lo_f = z - delta; hi_f = z + delta;
    }

    const unsigned long long NEG1 = 0xBF800000BF800000ull;   // (-1.0f, -1.0f)
    unsigned long long HI2, LO2;
    {
        unsigned hu = __float_as_uint(hi_f), lu = __float_as_uint(lo_f);
        HI2 = ((unsigned long long)hu << 32) | hu;
        LO2 = ((unsigned long long)lu << 32) | lu;
    }

    unsigned long long* myc = g_cand + (size_t)ch * HW_ + (size_t)tid * SLOTS_;
    unsigned* gbch = g_bitmap + (size_t)ch * 8192;
    unsigned cnt_hi, m;
    int mycap;
    for (int attempt = 0; ; attempt++) {
        if (tid == 0) { aux[0] = 0; aux[1] = 0; }
        __syncthreads();
        unsigned mycnt = 0;
        mycap = 0;
        #pragma unroll 1
        for (int ob = 0; ob < 8; ob++) {           // 8 outer blocks of 8*NT_ float4s
            int base = ob * 8 * NT_;
            ulonglong2 v0 = p[base + tid];
            ulonglong2 v1 = p[base + NT_ + tid];
            ulonglong2 v2 = p[base + 2 * NT_ + tid];
            ulonglong2 v3 = p[base + 3 * NT_ + tid];
            ulonglong2 v4 = p[base + 4 * NT_ + tid];
            ulonglong2 v5 = p[base + 5 * NT_ + tid];
            ulonglong2 v6 = p[base + 6 * NT_ + tid];
            ulonglong2 v7 = p[base + 7 * NT_ + tid];
            unsigned word = 0;
            #pragma unroll
            for (int j = 0; j < 8; j++) {
                ulonglong2 v = (j == 0) ? v0 : (j == 1) ? v1 : (j == 2) ? v2 : (j == 3) ? v3
                             : (j == 4) ? v4 : (j == 5) ? v5 : (j == 6) ? v6 : v7;
                // sign(hi - v) per lane: 1 FFMA2 per 2 elements
                unsigned hi4 = mm4(fma2(v.x, NEG1, HI2), fma2(v.y, NEG1, HI2));
                unsigned lo4 = mm4(fma2(v.x, NEG1, LO2), fma2(v.y, NEG1, LO2));
                word |= hi4 << (j * 4);
                unsigned cn = lo4 & ~hi4;
                if (cn) {                           // rare (~0.2-2%)
                    int idx4 = base + j * NT_ + tid;
                    float fx = __uint_as_float((unsigned)v.x);
                    float fy = __uint_as_float((unsigned)(v.x >> 32));
                    float fz = __uint_as_float((unsigned)v.y);
                    float fw = __uint_as_float((unsigned)(v.y >> 32));
                    if (cn & 1u) myc[mycap++] = ((unsigned long long)f2key(fx) << 32) | (unsigned)(idx4 * 4 + 0);
                    if (cn & 2u) myc[mycap++] = ((unsigned long long)f2key(fy) << 32) | (unsigned)(idx4 * 4 + 1);
                    if (cn & 4u) myc[mycap++] = ((unsigned long long)f2key(fz) << 32) | (unsigned)(idx4 * 4 + 2);
                    if (cn & 8u) myc[mycap++] = ((unsigned long long)f2key(fw) << 32) | (unsigned)(idx4 * 4 + 3);
                }
            }
            mycnt += __popc(word);
            gbch[ob * NT_ + tid] = word;            // coalesced, no cross-lane ops
        }
        // Block totals
        unsigned mc = (unsigned)mycap;
        #pragma unroll
        for (int off = 16; off; off >>= 1) {
            mycnt += __shfl_down_sync(0xffffffffu, mycnt, off);
            mc    += __shfl_down_sync(0xffffffffu, mc, off);
        }
        if (lane == 0) { atomicAdd(&aux[0], mycnt); atomicAdd(&aux[1], mc); }
        __syncthreads();
        cnt_hi = aux[0]; m = aux[1];
        if (k0) break;
        if ((cnt_hi < (unsigned)k && cnt_hi + m >= (unsigned)k) || attempt >= 1) break;
        lo_f = -INF; hi_f = INF;       // deterministic widen (count-check guarantee)
        {
            unsigned hu = __float_as_uint(hi_f), lu = __float_as_uint(lo_f);
            HI2 = ((unsigned long long)hu << 32) | hu;
            LO2 = ((unsigned long long)lu << 32) | lu;
        }
        __syncthreads();
    }

    // ---- exact threshold among candidates (11+11+10-bit radix), then fixups ----
    if (!k0) {
        unsigned r = (unsigned)k - cnt_hi;
        for (int i = tid; i < 2048; i += NT_) hist[i] = 0;
        __syncthreads();
        for (int i = 0; i < mycap; i++)
            atomicAdd(&hist[(unsigned)(myc[i] >> 32) >> 21], 1u);
        __syncthreads();
        block_find_bin(hist, 2048, r, sgrp, aux, tid, lane, w);
        unsigned bA = aux[0], rA = aux[1];
        __syncthreads();

        for (int i = tid; i < 2048; i += NT_) hist[i] = 0;
        __syncthreads();
        for (int i = 0; i < mycap; i++) {
            unsigned key = (unsigned)(myc[i] >> 32);
            if ((key >> 21) == bA) atomicAdd(&hist[(key >> 10) & 0x7FFu], 1u);
        }
        __syncthreads();
        block_find_bin(hist, 2048, rA, sgrp, aux, tid, lane, w);
        unsigned bB = aux[0], rB = aux[1];
        __syncthreads();

        for (int i = tid; i < 1024; i += NT_) hist[i] = 0;
        __syncthreads();
        for (int i = 0; i < mycap; i++) {
            unsigned key = (unsigned)(myc[i] >> 32);
            if ((key >> 21) == bA && ((key >> 10) & 0x7FFu) == bB)
                atomicAdd(&hist[key & 0x3FFu], 1u);
        }
        __syncthreads();
        block_find_bin(hist, 1024, rB, sgrp, aux, tid, lane, w);
        unsigned thrkey = (bA << 21) | (bB << 10) | aux[0];    // exact k-th largest
        __syncthreads();

        // Fixups: candidates above exact threshold -> set bit in bitmap
        for (int i = 0; i < mycap; i++) {
            unsigned long long cc = myc[i];
            if ((unsigned)(cc >> 32) > thrkey) {
                unsigned pos = (unsigned)cc & 0x3FFFFu;
                unsigned f4 = pos >> 2, e = pos & 3u;
                unsigned t  = f4 & 1023u, j = (f4 >> 10) & 7u, ob = f4 >> 13;
                atomicOr(&gbch[ob * NT_ + t], 1u << (j * 4 + e));
            }
        }
    }

    // ---- software grid barrier (144 resident CTAs; graph-replay safe) ----
    __threadfence();
    __syncthreads();
    if (tid == 0) {
        unsigned gen = *(volatile unsigned*)&g_bar_flag;
        unsigned t = atomicAdd(&g_bar_cnt, 1u);
        if (t == NCH_ - 1) {
            atomicExch(&g_bar_cnt, 0u);          // reset for next graph replay
            __threadfence();
            atomicAdd(&g_bar_flag, 1u);
        } else {
            while (*(volatile unsigned*)&g_bar_flag == gen) __nanosleep(64);
        }
        __threadfence();
    }
    __syncthreads();

    // ---- phase 2: per-thread OR of 9 channel words, apply to 8 float4s of x ----
    int gidx = blockIdx.x * NT_ + tid;               // 147456 threads, 131072 items
    if (gidx < N_ * 8192) {
        int nn = gidx >> 13;
        int wp = gidx & 8191;
        int ob = wp >> 10, t = wp & 1023;
        const unsigned* bm = g_bitmap + (size_t)nn * C_ * 8192 + wp;
        unsigned wrd = 0;
        #pragma unroll
        for (int c = 0; c < C_; c++) wrd |= __ldg(bm + (size_t)c * 8192);
        const float4* xp = (const float4*)x + ((size_t)nn << 16) + ob * 8192 + t;
        float4*       op = (float4*)out     + ((size_t)nn << 16) + ob * 8192 + t;
        #pragma unroll
        for (int j = 0; j < 8; j++) {
            float4 xv = xp[j * 1024];
            unsigned nib = (wrd >> (j * 4)) & 0xFu;
            float4 o;
            o.x = (nib & 1u) ? 0.0f : xv.x;
            o.y = (nib & 2u) ? 0.0f : xv.y;
            o.z = (nib & 4u) ? 0.0f : xv.z;
            o.w = (nib & 8u) ? 0.0f : xv.w;
            op[j * 1024] = o;
        }
    }
}

extern "C" void kernel_launch(void* const* d_in, const int* in_sizes, int n_in,
                              void* d_out, int out_size) {
    const float* inp   = (const float*)d_in[0];   // [16,9,512,512]
    const float* x     = (const float*)d_in[1];   // [16,1,512,512]
    const float* ratio = (const float*)d_in[2];   // [16]
    float* out = (float*)d_out;

    k_fused<<<NCH_, NT_>>>(inp, ratio, x, out);
}